// round 1
// baseline (speedup 1.0000x reference)
#include <cuda_runtime.h>
#include <math_constants.h>

#define BATCH 64
#define N 1024

// Scratch vectors: row offsets R[b][i], col offsets C[b][j]
__device__ float g_R[BATCH * N];
__device__ float g_C[BATCH * N];

// ---------------------------------------------------------------------------
// Row pass: R[b][i] = logsumexp_j( s[b][i][j] - (USE_C ? C[b][j] : 0) )
// One warp per row. 256 threads = 8 rows per CTA. grid = (128, 64).
// ---------------------------------------------------------------------------
template <bool USE_C>
__global__ void __launch_bounds__(256) row_pass(const float* __restrict__ s) {
    __shared__ float c_s[N];
    const int b = blockIdx.y;
    if (USE_C) {
        #pragma unroll
        for (int t = threadIdx.x; t < N; t += 256) c_s[t] = g_C[b * N + t];
        __syncthreads();
    }
    const int warp = threadIdx.x >> 5;
    const int lane = threadIdx.x & 31;
    const int row  = (blockIdx.x << 3) + warp;
    const float* p = s + ((size_t)b << 20) + ((size_t)row << 10);

    float v[32];
    #pragma unroll
    for (int k = 0; k < 8; k++) {
        const int j = (lane << 2) + (k << 7);   // 4*lane + 128*k
        float4 sv = *reinterpret_cast<const float4*>(p + j);
        if (USE_C) {
            float4 cv = *reinterpret_cast<const float4*>(&c_s[j]);
            sv.x -= cv.x; sv.y -= cv.y; sv.z -= cv.z; sv.w -= cv.w;
        }
        v[4 * k + 0] = sv.x; v[4 * k + 1] = sv.y;
        v[4 * k + 2] = sv.z; v[4 * k + 3] = sv.w;
    }
    float m = v[0];
    #pragma unroll
    for (int k = 1; k < 32; k++) m = fmaxf(m, v[k]);
    float acc = 0.f;
    #pragma unroll
    for (int k = 0; k < 32; k++) acc += __expf(v[k] - m);

    // warp-level combine of (m, acc) pairs
    #pragma unroll
    for (int off = 16; off; off >>= 1) {
        float om = __shfl_xor_sync(0xffffffffu, m, off);
        float oa = __shfl_xor_sync(0xffffffffu, acc, off);
        float M = fmaxf(m, om);
        acc = acc * __expf(m - M) + oa * __expf(om - M);
        m = M;
    }
    if (lane == 0) g_R[b * N + row] = m + logf(acc);
}

// ---------------------------------------------------------------------------
// Col pass: C[b][j] = logsumexp_i( s[b][i][j] - R[b][i] )
// CTA = (batch, 32-column slab). 256 threads as (x=32 cols, y=8 row-groups).
// Each thread streams 128 elements of its column in 16-element register
// chunks (amortized online-rescale: 17 exps / 16 elems). grid = (32, 64).
// ---------------------------------------------------------------------------
__global__ void __launch_bounds__(256) col_pass(const float* __restrict__ s) {
    __shared__ float r_s[N];
    __shared__ float sm_m[8][33];
    __shared__ float sm_a[8][33];
    const int b  = blockIdx.y;
    const int j0 = blockIdx.x << 5;
    #pragma unroll
    for (int t = threadIdx.x; t < N; t += 256) r_s[t] = g_R[b * N + t];
    __syncthreads();

    const int x = threadIdx.x & 31;
    const int y = threadIdx.x >> 5;
    const float* p = s + ((size_t)b << 20) + j0 + x;

    float m = -CUDART_INF_F, acc = 0.f;
    for (int rb = 0; rb < N; rb += 128) {
        float v[16];
        #pragma unroll
        for (int t = 0; t < 16; t++) {
            const int r = rb + y + (t << 3);
            v[t] = p[(size_t)r << 10] - r_s[r];
        }
        float cm = v[0];
        #pragma unroll
        for (int t = 1; t < 16; t++) cm = fmaxf(cm, v[t]);
        const float M = fmaxf(m, cm);
        acc *= __expf(m - M);                    // exp(-inf)=0 handles first chunk
        #pragma unroll
        for (int t = 0; t < 16; t++) acc += __expf(v[t] - M);
        m = M;
    }
    sm_m[y][x] = m; sm_a[y][x] = acc;
    __syncthreads();
    if (y == 0) {
        #pragma unroll
        for (int t = 1; t < 8; t++) {
            const float om = sm_m[t][x], oa = sm_a[t][x];
            const float M = fmaxf(m, om);
            acc = acc * __expf(m - M) + oa * __expf(om - M);
            m = M;
        }
        g_C[b * N + j0 + x] = m + logf(acc);
    }
}

// ---------------------------------------------------------------------------
// Output pass: out = exp(s - R[b][i] - C[b][j]), float4 vectorized.
// ---------------------------------------------------------------------------
__global__ void __launch_bounds__(256) out_pass(const float4* __restrict__ s4,
                                                float4* __restrict__ o4) {
    const size_t gid  = (size_t)blockIdx.x * 256 + threadIdx.x;
    const size_t base = gid << 2;
    const int b = (int)(base >> 20);
    const int i = (int)(base >> 10) & (N - 1);
    const int j = (int)base & (N - 1);
    const float r = __ldg(&g_R[(b << 10) + i]);
    const float4 c = *reinterpret_cast<const float4*>(&g_C[(b << 10) + j]);
    float4 v = s4[gid];
    float4 o;
    o.x = __expf(v.x - r - c.x);
    o.y = __expf(v.y - r - c.y);
    o.z = __expf(v.z - r - c.z);
    o.w = __expf(v.w - r - c.w);
    o4[gid] = o;
}

// ---------------------------------------------------------------------------
extern "C" void kernel_launch(void* const* d_in, const int* in_sizes, int n_in,
                              void* d_out, int out_size) {
    const float* s = (const float*)d_in[0];
    float* out = (float*)d_out;

    const dim3 row_grid(N / 8, BATCH);   // warp-per-row, 8 rows/CTA
    const dim3 col_grid(N / 32, BATCH);  // 32-col slab per CTA
    const int out_blocks = (BATCH * N * N / 4) / 256;

    // iter 0 (row, C == 0)
    row_pass<false><<<row_grid, 256>>>(s);
    // iters 1..9 alternate col/row
    col_pass<<<col_grid, 256>>>(s);      // iter 1
    row_pass<true><<<row_grid, 256>>>(s);// iter 2
    col_pass<<<col_grid, 256>>>(s);      // iter 3
    row_pass<true><<<row_grid, 256>>>(s);// iter 4
    col_pass<<<col_grid, 256>>>(s);      // iter 5
    row_pass<true><<<row_grid, 256>>>(s);// iter 6
    col_pass<<<col_grid, 256>>>(s);      // iter 7
    row_pass<true><<<row_grid, 256>>>(s);// iter 8
    col_pass<<<col_grid, 256>>>(s);      // iter 9

    out_pass<<<out_blocks, 256>>>((const float4*)s, (float4*)out);
}

// round 3
// speedup vs baseline: 1.4765x; 1.4765x over previous
#include <cuda_runtime.h>
#include <math_constants.h>

#define BATCH 64
#define N 1024
#define RBLKS 32            // row-blocks per batch (32 rows each)

// Scratch: row offsets R[b][i], col offsets C[b][j], per-CTA column partials
__device__ float g_R[BATCH * N];
__device__ float g_C[BATCH * N];
__device__ float g_part[BATCH * RBLKS * N];   // 8 MB

// ---------------------------------------------------------------------------
// Fused pass: for each row i in this CTA's 32-row block:
//   sum_i = sum_j exp(s[i][j] - C[j]);  R[i] = log(sum_i)   (replacement form)
// then accumulate column partials  part[j] += sum_i exp(s[i][j] - C[j] - R[i])
// finalize_col later forms C_new[j] = log(sum_blocks part) + C_old[j]
//   (= logsumexp_i(s_ij - R_i), the correct replacement column offset).
// Warp-per-row, 4 groups of 8 rows. grid = (RBLKS, BATCH), block = 256.
// No max-subtraction needed: exp args bounded (logsumexp >= max).
// ---------------------------------------------------------------------------
template <bool USE_C>
__global__ void __launch_bounds__(256) fused_pass(const float* __restrict__ s) {
    __shared__ float c_s[N];
    __shared__ float stage[8 * N];     // 32 KB: per-warp scaled-exp staging
    const int b = blockIdx.y;
    if (USE_C) {
        #pragma unroll
        for (int t = threadIdx.x; t < N; t += 256) c_s[t] = g_C[b * N + t];
    }
    __syncthreads();

    const int warp = threadIdx.x >> 5;
    const int lane = threadIdx.x & 31;
    const int tid  = threadIdx.x;

    float4 cacc = make_float4(0.f, 0.f, 0.f, 0.f);   // this thread's 4 columns

    #pragma unroll 1
    for (int g = 0; g < 4; g++) {
        const int row = (blockIdx.x << 5) + (g << 3) + warp;
        const float* p = s + ((size_t)b << 20) + ((size_t)row << 10);

        float e[32];
        float sum = 0.f;
        #pragma unroll
        for (int k = 0; k < 8; k++) {
            const int j = (lane << 2) + (k << 7);
            float4 sv = *reinterpret_cast<const float4*>(p + j);
            if (USE_C) {
                float4 cv = *reinterpret_cast<const float4*>(&c_s[j]);
                sv.x -= cv.x; sv.y -= cv.y; sv.z -= cv.z; sv.w -= cv.w;
            }
            e[4*k+0] = __expf(sv.x); e[4*k+1] = __expf(sv.y);
            e[4*k+2] = __expf(sv.z); e[4*k+3] = __expf(sv.w);
            sum += e[4*k+0] + e[4*k+1] + e[4*k+2] + e[4*k+3];
        }
        #pragma unroll
        for (int off = 16; off; off >>= 1)
            sum += __shfl_xor_sync(0xffffffffu, sum, off);

        if (lane == 0) g_R[b * N + row] = logf(sum);  // last pass's R feeds out_pass
        const float rinv = 1.f / sum;

        // stage scaled exps: exp(v - R) = e[k] * rinv
        #pragma unroll
        for (int k = 0; k < 8; k++) {
            const int j = (lane << 2) + (k << 7);
            float4 ev = make_float4(e[4*k+0]*rinv, e[4*k+1]*rinv,
                                    e[4*k+2]*rinv, e[4*k+3]*rinv);
            *reinterpret_cast<float4*>(&stage[warp * N + j]) = ev;
        }
        __syncthreads();

        // each thread reduces 8 warps for its 4 columns (cols 4*tid..4*tid+3)
        #pragma unroll
        for (int w = 0; w < 8; w++) {
            float4 sv = *reinterpret_cast<const float4*>(&stage[w * N + (tid << 2)]);
            cacc.x += sv.x; cacc.y += sv.y; cacc.z += sv.z; cacc.w += sv.w;
        }
        __syncthreads();   // before next group's staging overwrite
    }

    float4* pp = reinterpret_cast<float4*>(
        &g_part[((size_t)(b * RBLKS + blockIdx.x)) * N]);
    pp[tid] = cacc;
}

// ---------------------------------------------------------------------------
// Finalize: C_new[b][j] = log( sum over 32 row-block partials ) + C_old[b][j].
// FIRST=true: the pass ran with C==0, so write log(sum) directly (and must NOT
// read g_C — it holds stale values from the previous graph replay).
// ---------------------------------------------------------------------------
template <bool FIRST>
__global__ void __launch_bounds__(256) finalize_col() {
    const int idx = blockIdx.x * 256 + threadIdx.x;   // b*N + j
    const int b = idx >> 10, j = idx & (N - 1);
    float sum = 0.f;
    #pragma unroll
    for (int r = 0; r < RBLKS; r++)
        sum += g_part[((size_t)(b * RBLKS + r)) * N + j];
    if (FIRST) g_C[idx] = logf(sum);
    else       g_C[idx] = logf(sum) + g_C[idx];
}

// ---------------------------------------------------------------------------
// Output pass: out = exp(s - R[b][i] - C[b][j]), float4 vectorized.
// ---------------------------------------------------------------------------
__global__ void __launch_bounds__(256) out_pass(const float4* __restrict__ s4,
                                                float4* __restrict__ o4) {
    const size_t gid  = (size_t)blockIdx.x * 256 + threadIdx.x;
    const size_t base = gid << 2;
    const int b = (int)(base >> 20);
    const int i = (int)(base >> 10) & (N - 1);
    const int j = (int)base & (N - 1);
    const float r = __ldg(&g_R[(b << 10) + i]);
    const float4 c = *reinterpret_cast<const float4*>(&g_C[(b << 10) + j]);
    float4 v = s4[gid];
    float4 o;
    o.x = __expf(v.x - r - c.x);
    o.y = __expf(v.y - r - c.y);
    o.z = __expf(v.z - r - c.z);
    o.w = __expf(v.w - r - c.w);
    o4[gid] = o;
}

// ---------------------------------------------------------------------------
extern "C" void kernel_launch(void* const* d_in, const int* in_sizes, int n_in,
                              void* d_out, int out_size) {
    const float* s = (const float*)d_in[0];
    float* out = (float*)d_out;

    const dim3 fgrid(RBLKS, BATCH);
    const int fin_blocks = BATCH * N / 256;
    const int out_blocks = (BATCH * N * N / 4) / 256;

    // iters 0+1
    fused_pass<false><<<fgrid, 256>>>(s);
    finalize_col<true><<<fin_blocks, 256>>>();
    // iters 2+3, 4+5, 6+7, 8+9
    fused_pass<true><<<fgrid, 256>>>(s);
    finalize_col<false><<<fin_blocks, 256>>>();
    fused_pass<true><<<fgrid, 256>>>(s);
    finalize_col<false><<<fin_blocks, 256>>>();
    fused_pass<true><<<fgrid, 256>>>(s);
    finalize_col<false><<<fin_blocks, 256>>>();
    fused_pass<true><<<fgrid, 256>>>(s);
    finalize_col<false><<<fin_blocks, 256>>>();

    out_pass<<<out_blocks, 256>>>((const float4*)s, (float4*)out);
}